// round 7
// baseline (speedup 1.0000x reference)
#include <cuda_runtime.h>
#include <math.h>

#define N_TOK 4096
#define D_DIM 2048
#define N_EXP 8
#define TOPK  2
#define CAP   512
#define PITCH 1028                 // padded smem row (floats)
#define BLK   256
#define GRID1 256                  // 256 blk * 8 warps * 2 tok = 4096

__device__ int g_choice[N_TOK * TOPK];
__device__ int g_slot[N_TOK * TOPK];
__device__ unsigned int g_done;    // epoch counter (never reset; replay-safe)

// ---------------------------------------------------------------------------
// Kernel 1: logits GEMM + top-2 + softmax. 2 tokens/warp, 2 blocks/SM.
// Per phase: ALL 16 x-loads issued before compute (deep MLP).
// The last block to finish runs the per-(k,e) capacity scan (ballot+popc).
// ---------------------------------------------------------------------------
__global__ __launch_bounds__(BLK, 2) void k_gemm_scan(
        const float* __restrict__ x,
        const float* __restrict__ W,
        float* __restrict__ out) {
    __shared__ float wt[N_EXP * PITCH];   // 32.9 KB -> 2 blocks/SM fits easily
    __shared__ bool amLast;

    int tid  = threadIdx.x;
    int lane = tid & 31;
    int wrp  = tid >> 5;
    int t0   = (blockIdx.x * 8 + wrp) * 2;

    const float4* x4 = reinterpret_cast<const float4*>(x);
    float acc0[N_EXP] = {0,0,0,0,0,0,0,0};
    float acc1[N_EXP] = {0,0,0,0,0,0,0,0};

    for (int p = 0; p < 2; p++) {
        // stage W[p*1024 .. +1024) transposed: wt[e][d] (conflict-free)
        for (int idx = tid; idx < 1024 * N_EXP; idx += BLK) {
            int dl = idx >> 3;
            int e  = idx & 7;
            wt[e * PITCH + dl] = W[(p * 1024 + dl) * N_EXP + e];
        }
        __syncthreads();

        // batch all 16 loads -> deep MLP
        float4 xa[8], xb[8];
        #pragma unroll
        for (int i = 0; i < 8; i++) {
            int j = i * 32 + lane;
            xa[i] = __ldcs(&x4[(size_t)t0       * (D_DIM/4) + p * 256 + j]);
            xb[i] = __ldcs(&x4[(size_t)(t0 + 1) * (D_DIM/4) + p * 256 + j]);
        }
        #pragma unroll
        for (int i = 0; i < 8; i++) {
            int j = i * 32 + lane;
            #pragma unroll
            for (int e = 0; e < N_EXP; e++) {
                float4 w = *reinterpret_cast<const float4*>(&wt[e * PITCH + j * 4]);
                acc0[e] += xa[i].x * w.x + xa[i].y * w.y + xa[i].z * w.z + xa[i].w * w.w;
                acc1[e] += xb[i].x * w.x + xb[i].y * w.y + xb[i].z * w.z + xb[i].w * w.w;
            }
        }
        __syncthreads();
    }

    #pragma unroll
    for (int e = 0; e < N_EXP; e++) {
        #pragma unroll
        for (int off = 16; off > 0; off >>= 1) {
            acc0[e] += __shfl_xor_sync(0xffffffffu, acc0[e], off);
            acc1[e] += __shfl_xor_sync(0xffffffffu, acc1[e], off);
        }
    }

    if (lane == 0) {
        float* gate = out + (size_t)N_TOK * N_EXP * CAP;
        float* idxf = gate + N_TOK * TOPK;
        #pragma unroll
        for (int t = 0; t < 2; t++) {
            float* a = t ? acc1 : acc0;
            int tok = t0 + t;
            float best = -INFINITY, sec = -INFINITY;
            int bi = 0, si = 0;
            #pragma unroll
            for (int e = 0; e < N_EXP; e++) {
                float v = a[e];
                if (v > best)     { sec = best; si = bi; best = v; bi = e; }
                else if (v > sec) { sec = v;    si = e; }
            }
            float g0 = 1.0f / (1.0f + expf(sec - best));
            gate[tok * 2 + 0] = g0;
            gate[tok * 2 + 1] = 1.0f - g0;
            idxf[tok * 2 + 0] = (float)bi;
            idxf[tok * 2 + 1] = (float)si;
            g_choice[tok * 2 + 0] = bi;
            g_choice[tok * 2 + 1] = si;
        }
        __threadfence();   // make this warp's g_choice writes globally visible
    }

    // ---- last-block-done election (epoch-safe across graph replays) ----
    __syncthreads();
    if (tid == 0) {
        unsigned int old = atomicAdd(&g_done, 1u);
        amLast = ((old % GRID1) == (GRID1 - 1));
    }
    __syncthreads();
    if (!amLast) return;
    __threadfence();

    // ---- scan: 16 (k,e) pairs over 8 warps, ballot+popc, 32 tok/step ----
    for (int pair = wrp; pair < 16; pair += 8) {
        int k = pair >> 3;
        int e = pair & 7;
        unsigned int ltmask = (1u << lane) - 1u;
        int running = 0;
        #pragma unroll 4
        for (int c = 0; c < N_TOK / 32; c++) {
            int tok = c * 32 + lane;
            bool flag = (g_choice[tok * 2 + k] == e);
            unsigned int m = __ballot_sync(0xffffffffu, flag);
            if (flag) {
                int pri0 = running + __popc(m & ltmask);    // 0-based priority
                g_slot[tok * 2 + k] = (pri0 < CAP) ? pri0 : -1;
            }
            running += __popc(m);
        }
    }
}

// ---------------------------------------------------------------------------
// Kernel 2: fused zero + scatter. One block per token row (8*512 floats),
// pure coalesced streaming stores; values derived from the 2 (expert,slot).
// ---------------------------------------------------------------------------
__global__ __launch_bounds__(BLK) void k_fill(float4* __restrict__ out) {
    int n   = blockIdx.x;
    int tid = threadIdx.x;

    int c0 = g_choice[n * 2 + 0];
    int c1 = g_choice[n * 2 + 1];
    int s0 = g_slot[n * 2 + 0];
    int s1 = g_slot[n * 2 + 1];
    int o0 = (s0 >= 0) ? c0 * CAP + s0 : -1;   // float index within row
    int o1 = (s1 >= 0) ? c1 * CAP + s1 : -1;

    float4* row = out + (size_t)n * (N_EXP * CAP / 4);

    #pragma unroll
    for (int q = 0; q < 4; q++) {
        int g = q * BLK + tid;         // float4 index within row [0,1024)
        int f = g * 4;
        float4 v;
        v.x = (o0 == f     || o1 == f    ) ? 1.0f : 0.0f;
        v.y = (o0 == f + 1 || o1 == f + 1) ? 1.0f : 0.0f;
        v.z = (o0 == f + 2 || o1 == f + 2) ? 1.0f : 0.0f;
        v.w = (o0 == f + 3 || o1 == f + 3) ? 1.0f : 0.0f;
        __stcs(&row[g], v);
    }
}

// ---------------------------------------------------------------------------
extern "C" void kernel_launch(void* const* d_in, const int* in_sizes, int n_in,
                              void* d_out, int out_size) {
    const float* x = (const float*)d_in[0];   // [4096, 2048]
    const float* W = (const float*)d_in[1];   // [2048, 8]
    float* out = (float*)d_out;

    k_gemm_scan<<<GRID1, BLK>>>(x, W, out);
    k_fill<<<N_TOK, BLK>>>((float4*)out);
}

// round 8
// speedup vs baseline: 2.2472x; 2.2472x over previous
#include <cuda_runtime.h>
#include <math.h>

#define N_TOK 4096
#define D_DIM 2048
#define N_EXP 8
#define TOPK  2
#define CAP   512
#define PITCH 1028   // padded smem row (floats)

// Scratch (static device globals — no allocation)
__device__ int g_choice[N_TOK * TOPK];
__device__ int g_slot[N_TOK * TOPK];

// ---------------------------------------------------------------------------
// Kernel 1: logits = x @ W, top-2, softmax. 2 tokens per warp.
// W staged transposed in smem (conflict-free float4 LDS).
// launch_bounds(256,2): 128-reg cap -> 2 blocks/SM (16 warps), and 4-deep
// explicit load batching -> 8 LDG.128 in flight per warp. Fixes the
// MLP*occupancy limit that pinned R2's k1 at 2.2 TB/s.
// ---------------------------------------------------------------------------
__global__ __launch_bounds__(256, 2) void k_logits_topk(
        const float* __restrict__ x,
        const float* __restrict__ W,
        float* __restrict__ out) {
    __shared__ float wt[N_EXP * PITCH];   // 8 x 1028 floats = 32.9 KB

    int tid  = threadIdx.x;
    int lane = tid & 31;
    int wrp  = tid >> 5;
    int gw   = blockIdx.x * 8 + wrp;     // global warp id, 0..2047
    int t0   = gw * 2;                   // first of 2 tokens

    const float4* x4 = reinterpret_cast<const float4*>(x);

    float acc0[8] = {0,0,0,0,0,0,0,0};
    float acc1[8] = {0,0,0,0,0,0,0,0};

    for (int p = 0; p < 2; p++) {        // two 1024-d phases
        // cooperative transpose-load of W[p*1024 .. +1024)[e] -> wt[e][d]
        for (int idx = tid; idx < 1024 * N_EXP; idx += 256) {
            int dl = idx >> 3;
            int e  = idx & 7;
            wt[e * PITCH + dl] = W[(p * 1024 + dl) * N_EXP + e];
        }
        __syncthreads();

        #pragma unroll
        for (int ib = 0; ib < 2; ib++) {
            // 4-deep load batch: 8 LDG.128 in flight (2 tokens x 4)
            float4 xa[4], xb[4];
            #pragma unroll
            for (int u = 0; u < 4; u++) {
                int j = (ib * 4 + u) * 32 + lane;   // float4 idx in phase [0,256)
                xa[u] = __ldg(&x4[(size_t)t0       * (D_DIM/4) + p * 256 + j]);
                xb[u] = __ldg(&x4[(size_t)(t0 + 1) * (D_DIM/4) + p * 256 + j]);
            }
            #pragma unroll
            for (int u = 0; u < 4; u++) {
                int j = (ib * 4 + u) * 32 + lane;
                #pragma unroll
                for (int e = 0; e < N_EXP; e++) {
                    float4 w = *reinterpret_cast<const float4*>(&wt[e * PITCH + j * 4]);
                    acc0[e] += xa[u].x * w.x + xa[u].y * w.y + xa[u].z * w.z + xa[u].w * w.w;
                    acc1[e] += xb[u].x * w.x + xb[u].y * w.y + xb[u].z * w.z + xb[u].w * w.w;
                }
            }
        }
        __syncthreads();
    }

    // warp-reduce all 16 logits
    #pragma unroll
    for (int e = 0; e < N_EXP; e++) {
        #pragma unroll
        for (int off = 16; off > 0; off >>= 1) {
            acc0[e] += __shfl_xor_sync(0xffffffffu, acc0[e], off);
            acc1[e] += __shfl_xor_sync(0xffffffffu, acc1[e], off);
        }
    }

    if (lane == 0) {
        float* gate = out + (size_t)N_TOK * N_EXP * CAP;
        float* idxf = gate + N_TOK * TOPK;
        #pragma unroll
        for (int t = 0; t < 2; t++) {
            float* a = t ? acc1 : acc0;
            int tok = t0 + t;
            float best = -INFINITY, sec = -INFINITY;
            int bi = 0, si = 0;
            #pragma unroll
            for (int e = 0; e < N_EXP; e++) {
                float v = a[e];
                if (v > best)     { sec = best; si = bi; best = v; bi = e; }
                else if (v > sec) { sec = v;    si = e; }
            }
            float g0 = 1.0f / (1.0f + expf(sec - best));
            gate[tok * 2 + 0] = g0;
            gate[tok * 2 + 1] = 1.0f - g0;
            idxf[tok * 2 + 0] = (float)bi;
            idxf[tok * 2 + 1] = (float)si;
            g_choice[tok * 2 + 0] = bi;
            g_choice[tok * 2 + 1] = si;
        }
    }
}

// ---------------------------------------------------------------------------
// Kernel 2: per-(k,expert) running-count prefix scan over 4096 tokens.
// 16 blocks (one per (k,e)), 1024 threads, 4 tokens/thread.  (R2-proven)
// ---------------------------------------------------------------------------
__global__ void k_scan() {
    int k = blockIdx.x >> 3;
    int e = blockIdx.x & 7;
    int tid  = threadIdx.x;
    int lane = tid & 31;
    int wid  = tid >> 5;

    __shared__ int warp_sums[32];

    int n0 = tid * 4;
    int flags[4];
    int localex[4];
    int s = 0;
    #pragma unroll
    for (int j = 0; j < 4; j++) {
        flags[j]   = (g_choice[(n0 + j) * 2 + k] == e) ? 1 : 0;
        localex[j] = s;
        s += flags[j];
    }

    int inc = s;
    #pragma unroll
    for (int off = 1; off < 32; off <<= 1) {
        int v = __shfl_up_sync(0xffffffffu, inc, off);
        if (lane >= off) inc += v;
    }
    if (lane == 31) warp_sums[wid] = inc;
    __syncthreads();

    if (wid == 0) {
        int v = warp_sums[lane];
        int winc = v;
        #pragma unroll
        for (int off = 1; off < 32; off <<= 1) {
            int u = __shfl_up_sync(0xffffffffu, winc, off);
            if (lane >= off) winc += u;
        }
        warp_sums[lane] = winc - v;
    }
    __syncthreads();

    int thread_prefix = warp_sums[wid] + (inc - s);

    #pragma unroll
    for (int j = 0; j < 4; j++) {
        if (flags[j]) {
            int pri = thread_prefix + localex[j] + 1;
            g_slot[(n0 + j) * 2 + k] = (pri <= CAP) ? (pri - 1) : -1;
        }
    }
}

// ---------------------------------------------------------------------------
// Kernel 3 (fused zero+scatter): one block per token row (8*512 floats).
// Pure coalesced plain stores (proven faster than __stcs here). (R2-proven)
// ---------------------------------------------------------------------------
__global__ __launch_bounds__(256) void k_fill(float4* __restrict__ out) {
    int n   = blockIdx.x;
    int tid = threadIdx.x;

    int c0 = g_choice[n * 2 + 0];
    int c1 = g_choice[n * 2 + 1];
    int s0 = g_slot[n * 2 + 0];
    int s1 = g_slot[n * 2 + 1];
    int o0 = (s0 >= 0) ? c0 * CAP + s0 : -1;   // float index within row
    int o1 = (s1 >= 0) ? c1 * CAP + s1 : -1;

    float4* row = out + (size_t)n * (N_EXP * CAP / 4);

    #pragma unroll
    for (int q = 0; q < 4; q++) {
        int g = q * 256 + tid;         // float4 index within row [0,1024)
        int f = g * 4;                 // first float index
        float4 v;
        v.x = (o0 == f     || o1 == f    ) ? 1.0f : 0.0f;
        v.y = (o0 == f + 1 || o1 == f + 1) ? 1.0f : 0.0f;
        v.z = (o0 == f + 2 || o1 == f + 2) ? 1.0f : 0.0f;
        v.w = (o0 == f + 3 || o1 == f + 3) ? 1.0f : 0.0f;
        row[g] = v;
    }
}

// ---------------------------------------------------------------------------
extern "C" void kernel_launch(void* const* d_in, const int* in_sizes, int n_in,
                              void* d_out, int out_size) {
    const float* x = (const float*)d_in[0];   // [4096, 2048]
    const float* W = (const float*)d_in[1];   // [2048, 8]
    float* out = (float*)d_out;

    k_logits_topk<<<256, 256>>>(x, W, out);
    k_scan<<<16, 1024>>>();
    k_fill<<<N_TOK, 256>>>((float4*)out);
}

// round 9
// speedup vs baseline: 2.3841x; 1.0609x over previous
#include <cuda_runtime.h>
#include <math.h>

#define N_TOK 4096
#define D_DIM 2048
#define N_EXP 8
#define TOPK  2
#define CAP   512
#define PITCH 2052   // padded smem row (floats), conflict-free
#define BLK1  512
#define GRID1 128    // exactly 1 block/SM, single balanced wave

// Scratch (static device globals — no allocation)
__device__ int g_choice[N_TOK * TOPK];
__device__ int g_slot[N_TOK * TOPK];

// ---------------------------------------------------------------------------
// Kernel 1: logits = x @ W, top-2, softmax. 2 tokens per warp.
// 128 blocks x 512 threads -> 1 block/SM, 16 warps/SM, balanced single wave.
// Full W staged transposed in smem once (65.7 KB). 4-deep load batches give
// 8 LDG.128 in flight per warp -> ~512 lines in flight per SM.
// ---------------------------------------------------------------------------
__global__ __launch_bounds__(BLK1, 1) void k_logits_topk(
        const float* __restrict__ x,
        const float* __restrict__ W,
        float* __restrict__ out) {
    __shared__ float wt[N_EXP * PITCH];   // 65.7 KB

    int tid  = threadIdx.x;
    int lane = tid & 31;
    int wrp  = tid >> 5;
    int gw   = blockIdx.x * 16 + wrp;    // global warp id, 0..2047
    int t0   = gw * 2;                   // first of 2 tokens

    // stage ALL of W transposed: wt[e][d] (store: bank = (4e+d)%32 distinct)
    for (int idx = tid; idx < D_DIM * N_EXP; idx += BLK1) {
        int d = idx >> 3;
        int e = idx & 7;
        wt[e * PITCH + d] = W[idx];
    }
    __syncthreads();

    const float4* x4 = reinterpret_cast<const float4*>(x);
    const float4* xr0 = x4 + (size_t)t0 * (D_DIM / 4);
    const float4* xr1 = x4 + (size_t)(t0 + 1) * (D_DIM / 4);

    float acc0[8] = {0,0,0,0,0,0,0,0};
    float acc1[8] = {0,0,0,0,0,0,0,0};

    #pragma unroll
    for (int ib = 0; ib < 4; ib++) {
        // 4-deep load batch: 8 LDG.128 in flight (2 tokens x 4)
        float4 xa[4], xb[4];
        #pragma unroll
        for (int u = 0; u < 4; u++) {
            int j = (ib * 4 + u) * 32 + lane;   // float4 idx in [0,512)
            xa[u] = __ldg(&xr0[j]);
            xb[u] = __ldg(&xr1[j]);
        }
        #pragma unroll
        for (int u = 0; u < 4; u++) {
            int j = (ib * 4 + u) * 32 + lane;
            #pragma unroll
            for (int e = 0; e < N_EXP; e++) {
                float4 w = *reinterpret_cast<const float4*>(&wt[e * PITCH + j * 4]);
                acc0[e] += xa[u].x * w.x + xa[u].y * w.y + xa[u].z * w.z + xa[u].w * w.w;
                acc1[e] += xb[u].x * w.x + xb[u].y * w.y + xb[u].z * w.z + xb[u].w * w.w;
            }
        }
    }

    // warp-reduce all 16 logits
    #pragma unroll
    for (int e = 0; e < N_EXP; e++) {
        #pragma unroll
        for (int off = 16; off > 0; off >>= 1) {
            acc0[e] += __shfl_xor_sync(0xffffffffu, acc0[e], off);
            acc1[e] += __shfl_xor_sync(0xffffffffu, acc1[e], off);
        }
    }

    if (lane == 0) {
        float* gate = out + (size_t)N_TOK * N_EXP * CAP;
        float* idxf = gate + N_TOK * TOPK;
        #pragma unroll
        for (int t = 0; t < 2; t++) {
            float* a = t ? acc1 : acc0;
            int tok = t0 + t;
            float best = -INFINITY, sec = -INFINITY;
            int bi = 0, si = 0;
            #pragma unroll
            for (int e = 0; e < N_EXP; e++) {
                float v = a[e];
                if (v > best)     { sec = best; si = bi; best = v; bi = e; }
                else if (v > sec) { sec = v;    si = e; }
            }
            float g0 = 1.0f / (1.0f + expf(sec - best));
            gate[tok * 2 + 0] = g0;
            gate[tok * 2 + 1] = 1.0f - g0;
            idxf[tok * 2 + 0] = (float)bi;
            idxf[tok * 2 + 1] = (float)si;
            g_choice[tok * 2 + 0] = bi;
            g_choice[tok * 2 + 1] = si;
        }
    }
}

// ---------------------------------------------------------------------------
// Kernel 2: per-(k,expert) running-count prefix scan over 4096 tokens.
// 16 blocks (one per (k,e)), 1024 threads, 4 tokens/thread.  (R2-proven)
// ---------------------------------------------------------------------------
__global__ void k_scan() {
    int k = blockIdx.x >> 3;
    int e = blockIdx.x & 7;
    int tid  = threadIdx.x;
    int lane = tid & 31;
    int wid  = tid >> 5;

    __shared__ int warp_sums[32];

    int n0 = tid * 4;
    int flags[4];
    int localex[4];
    int s = 0;
    #pragma unroll
    for (int j = 0; j < 4; j++) {
        flags[j]   = (g_choice[(n0 + j) * 2 + k] == e) ? 1 : 0;
        localex[j] = s;
        s += flags[j];
    }

    int inc = s;
    #pragma unroll
    for (int off = 1; off < 32; off <<= 1) {
        int v = __shfl_up_sync(0xffffffffu, inc, off);
        if (lane >= off) inc += v;
    }
    if (lane == 31) warp_sums[wid] = inc;
    __syncthreads();

    if (wid == 0) {
        int v = warp_sums[lane];
        int winc = v;
        #pragma unroll
        for (int off = 1; off < 32; off <<= 1) {
            int u = __shfl_up_sync(0xffffffffu, winc, off);
            if (lane >= off) winc += u;
        }
        warp_sums[lane] = winc - v;
    }
    __syncthreads();

    int thread_prefix = warp_sums[wid] + (inc - s);

    #pragma unroll
    for (int j = 0; j < 4; j++) {
        if (flags[j]) {
            int pri = thread_prefix + localex[j] + 1;
            g_slot[(n0 + j) * 2 + k] = (pri <= CAP) ? (pri - 1) : -1;
        }
    }
}

// ---------------------------------------------------------------------------
// Kernel 3 (fused zero+scatter): one block per token row (8*512 floats).
// Pure coalesced plain stores. (R2-proven)
// ---------------------------------------------------------------------------
__global__ __launch_bounds__(256) void k_fill(float4* __restrict__ out) {
    int n   = blockIdx.x;
    int tid = threadIdx.x;

    int c0 = g_choice[n * 2 + 0];
    int c1 = g_choice[n * 2 + 1];
    int s0 = g_slot[n * 2 + 0];
    int s1 = g_slot[n * 2 + 1];
    int o0 = (s0 >= 0) ? c0 * CAP + s0 : -1;   // float index within row
    int o1 = (s1 >= 0) ? c1 * CAP + s1 : -1;

    float4* row = out + (size_t)n * (N_EXP * CAP / 4);

    #pragma unroll
    for (int q = 0; q < 4; q++) {
        int g = q * 256 + tid;         // float4 index within row [0,1024)
        int f = g * 4;                 // first float index
        float4 v;
        v.x = (o0 == f     || o1 == f    ) ? 1.0f : 0.0f;
        v.y = (o0 == f + 1 || o1 == f + 1) ? 1.0f : 0.0f;
        v.z = (o0 == f + 2 || o1 == f + 2) ? 1.0f : 0.0f;
        v.w = (o0 == f + 3 || o1 == f + 3) ? 1.0f : 0.0f;
        row[g] = v;
    }
}

// ---------------------------------------------------------------------------
extern "C" void kernel_launch(void* const* d_in, const int* in_sizes, int n_in,
                              void* d_out, int out_size) {
    const float* x = (const float*)d_in[0];   // [4096, 2048]
    const float* W = (const float*)d_in[1];   // [2048, 8]
    float* out = (float*)d_out;

    k_logits_topk<<<GRID1, BLK1>>>(x, W, out);
    k_scan<<<16, 1024>>>();
    k_fill<<<N_TOK, 256>>>((float4*)out);
}